// round 12
// baseline (speedup 1.0000x reference)
#include <cuda_runtime.h>
#include <cuda_fp16.h>
#include <cstdint>

// EnsembleRBF via mma.sync m16n8k16 fp16 (A fp16, B fp16, fp32 accum).
// out[m,n,d] = sum_c exp(-||x_n-c||^2) * sigma^2 * W[m,c,d]
// N=100000, C=256, D=2, M=5.
// R12: single kernel; B-fragment staging rebuilt with the float4 trick:
// one coalesced LDG.128 yields both (j=2m, j=2m+1) fp16 packs for a center
// pair -> ~10 staging instructions/thread (vs ~30 scattered in R8).

#define TPB 256
#define PTS_PER_BLOCK 128
#define C_CENTERS 256
#define HSTEPS 8
#define NSTEPS 16
#define CB_ST 130

__device__ __forceinline__ float ex2a(float v) {
    float r; asm("ex2.approx.ftz.f32 %0, %1;" : "=f"(r) : "f"(v)); return r;
}
// pack {upper=a, lower=b} as f16x2
__device__ __forceinline__ uint32_t hpack(float a, float b) {
    uint32_t d;
    asm("cvt.rn.f16x2.f32 %0, %1, %2;" : "=r"(d) : "f"(a), "f"(b));
    return d;
}

__device__ __forceinline__ void mma16816(float* c,
    uint32_t a0, uint32_t a1, uint32_t a2, uint32_t a3, uint32_t b0, uint32_t b1) {
    asm volatile(
        "mma.sync.aligned.m16n8k16.row.col.f32.f16.f16.f32 "
        "{%0,%1,%2,%3}, {%4,%5,%6,%7}, {%8,%9}, {%0,%1,%2,%3};"
        : "+f"(c[0]), "+f"(c[1]), "+f"(c[2]), "+f"(c[3])
        : "r"(a0), "r"(a1), "r"(a2), "r"(a3), "r"(b0), "r"(b1));
}

__global__ void __launch_bounds__(TPB)
rbf_mma_kernel(const float* __restrict__ x,
               const float* __restrict__ centers,
               const float* __restrict__ weights,
               float* __restrict__ out,
               int n) {
    // gtab[c] = (2*L2E*cx, 2*L2E*cy, -L2E*|c|^2, 0)
    __shared__ float4 gtab[C_CENTERS];                 // 4KB
    // B fragments [step][lane] -> uint4 {t0b0, t0b1, t1b0, t1b1} (fp16)
    __shared__ uint4 bfragH[NSTEPS * 32];              // 8KB
    __shared__ float cbuf[16 * CB_ST];                 // 8.1KB transpose + reduce

    const int tid = threadIdx.x;
    const int lane = tid & 31;
    const int w = tid >> 5;
    const int wq = w & 3;        // point-group within block
    const int chalf = w >> 2;    // which half of centers
    const float L2E = 1.4426950408889634f;

    // ---- stage gtab ----
    for (int c = tid; c < C_CENTERS; c += TPB) {
        const float2 cc = reinterpret_cast<const float2*>(centers)[c];
        gtab[c] = make_float4(2.0f * L2E * cc.x, 2.0f * L2E * cc.y,
                              -L2E * (cc.x * cc.x + cc.y * cc.y), 0.0f);
    }

    // ---- stage B fragments ----
    // Zero only the pad components (t=1, j>=10 i.e. l>>2 >= 2): 768 words,
    // disjoint from the fill writes below -> no sync needed in between.
    {
        uint32_t* bw = reinterpret_cast<uint32_t*>(bfragH);
        for (int e = tid; e < 16 * 24 * 2; e += TPB) {
            const int b = e & 1;
            const int r = e >> 1;
            const int lidx = r % 24;          // l = 8..31
            const int s = r / 24;
            bw[(s * 32 + (8 + lidx)) * 4 + 2 + b] = 0u;
        }
        // Fill: task = (m, keven). One float4 = both j=2m and j=2m+1 packs.
        for (int task = tid; task < 5 * 128; task += TPB) {
            const int m = task >> 7;          // 0..4
            const int keven = (task & 127) * 2;
            const float4 F = *reinterpret_cast<const float4*>(weights + m * 512 + keven * 2);
            const uint32_t p0 = hpack(F.z, F.x);   // j=2m:   {lower=W[k], upper=W[k+1]}
            const uint32_t p1 = hpack(F.w, F.y);   // j=2m+1
            const int s = keven >> 4;
            const int b = (keven >> 3) & 1;
            const int lquad = (keven & 7) >> 1;
            const int j0 = 2 * m, j1 = 2 * m + 1;
            const int idx0 = (s * 32 + (j0 & 7) * 4 + lquad) * 4 + (j0 >> 3) * 2 + b;
            const int idx1 = (s * 32 + (j1 & 7) * 4 + lquad) * 4 + (j1 >> 3) * 2 + b;
            bw[idx0] = p0;
            bw[idx1] = p1;
        }
    }
    __syncthreads();

    // ---- 4 points per lane: tile A rows (lp, lp+8), tile B rows (+16, +24) ----
    const int gbase = blockIdx.x * PTS_PER_BLOCK;
    const int lp = wq * 32 + (lane >> 2);
    const int q0 = gbase + lp;
    const float2 XA0 = reinterpret_cast<const float2*>(x)[q0 < n ? q0 : (n - 1)];
    const float2 XA1 = reinterpret_cast<const float2*>(x)[(q0 + 8) < n ? (q0 + 8) : (n - 1)];
    const float2 XB0 = reinterpret_cast<const float2*>(x)[(q0 + 16) < n ? (q0 + 16) : (n - 1)];
    const float2 XB1 = reinterpret_cast<const float2*>(x)[(q0 + 24) < n ? (q0 + 24) : (n - 1)];
    // per-point bias: -L2E*|x|^2 - 4  (sigma^2 = 2^-4 folded)
    const float tA0 = fmaf(fmaf(XA0.x, XA0.x, XA0.y * XA0.y), -L2E, -4.0f);
    const float tA1 = fmaf(fmaf(XA1.x, XA1.x, XA1.y * XA1.y), -L2E, -4.0f);
    const float tB0 = fmaf(fmaf(XB0.x, XB0.x, XB0.y * XB0.y), -L2E, -4.0f);
    const float tB1 = fmaf(fmaf(XB1.x, XB1.x, XB1.y * XB1.y), -L2E, -4.0f);

    const int kb = (lane & 3) * 2;

    float cA0[4] = {0.f, 0.f, 0.f, 0.f};  // tile A, cols 0-7
    float cA1[4] = {0.f, 0.f, 0.f, 0.f};  // tile A, cols 8-15
    float cB0[4] = {0.f, 0.f, 0.f, 0.f};  // tile B, cols 0-7
    float cB1[4] = {0.f, 0.f, 0.f, 0.f};  // tile B, cols 8-15

#pragma unroll
    for (int k = 0; k < HSTEPS; k++) {
        const int s = chalf * HSTEPS + k;
        const float4* gp = &gtab[s * 16 + kb];
        const float4 g0 = gp[0], g1 = gp[1], g2 = gp[8], g3 = gp[9];

        const float rA00 = ex2a(fmaf(XA0.x, g0.x, fmaf(XA0.y, g0.y, g0.z)) + tA0);
        const float rA01 = ex2a(fmaf(XA0.x, g1.x, fmaf(XA0.y, g1.y, g1.z)) + tA0);
        const float rA02 = ex2a(fmaf(XA0.x, g2.x, fmaf(XA0.y, g2.y, g2.z)) + tA0);
        const float rA03 = ex2a(fmaf(XA0.x, g3.x, fmaf(XA0.y, g3.y, g3.z)) + tA0);
        const float rA10 = ex2a(fmaf(XA1.x, g0.x, fmaf(XA1.y, g0.y, g0.z)) + tA1);
        const float rA11 = ex2a(fmaf(XA1.x, g1.x, fmaf(XA1.y, g1.y, g1.z)) + tA1);
        const float rA12 = ex2a(fmaf(XA1.x, g2.x, fmaf(XA1.y, g2.y, g2.z)) + tA1);
        const float rA13 = ex2a(fmaf(XA1.x, g3.x, fmaf(XA1.y, g3.y, g3.z)) + tA1);
        const float rB00 = ex2a(fmaf(XB0.x, g0.x, fmaf(XB0.y, g0.y, g0.z)) + tB0);
        const float rB01 = ex2a(fmaf(XB0.x, g1.x, fmaf(XB0.y, g1.y, g1.z)) + tB0);
        const float rB02 = ex2a(fmaf(XB0.x, g2.x, fmaf(XB0.y, g2.y, g2.z)) + tB0);
        const float rB03 = ex2a(fmaf(XB0.x, g3.x, fmaf(XB0.y, g3.y, g3.z)) + tB0);
        const float rB10 = ex2a(fmaf(XB1.x, g0.x, fmaf(XB1.y, g0.y, g0.z)) + tB1);
        const float rB11 = ex2a(fmaf(XB1.x, g1.x, fmaf(XB1.y, g1.y, g1.z)) + tB1);
        const float rB12 = ex2a(fmaf(XB1.x, g2.x, fmaf(XB1.y, g2.y, g2.z)) + tB1);
        const float rB13 = ex2a(fmaf(XB1.x, g3.x, fmaf(XB1.y, g3.y, g3.z)) + tB1);

        // A fragments: {upper = k+1 col, lower = k col}
        const uint32_t aA0 = hpack(rA01, rA00);
        const uint32_t aA1 = hpack(rA11, rA10);
        const uint32_t aA2 = hpack(rA03, rA02);
        const uint32_t aA3 = hpack(rA13, rA12);
        const uint32_t aB0 = hpack(rB01, rB00);
        const uint32_t aB1 = hpack(rB11, rB10);
        const uint32_t aB2 = hpack(rB03, rB02);
        const uint32_t aB3 = hpack(rB13, rB12);

        const uint4 BH = bfragH[s * 32 + lane];

        mma16816(cA0, aA0, aA1, aA2, aA3, BH.x, BH.y);
        mma16816(cA1, aA0, aA1, aA2, aA3, BH.z, BH.w);
        mma16816(cB0, aB0, aB1, aB2, aB3, BH.x, BH.y);
        mma16816(cB1, aB0, aB1, aB2, aB3, BH.z, BH.w);
    }

    // ---- epilogue: merge C-halves in the transpose buffer ----
    const int j0 = (lane & 3) * 2;
    const int pA0 = lp, pA1 = lp + 8, pB0 = lp + 16, pB1 = lp + 24;

    if (chalf == 0) {
        cbuf[(j0 + 0) * CB_ST + pA0] = cA0[0];
        cbuf[(j0 + 1) * CB_ST + pA0] = cA0[1];
        cbuf[(j0 + 0) * CB_ST + pA1] = cA0[2];
        cbuf[(j0 + 1) * CB_ST + pA1] = cA0[3];
        cbuf[(j0 + 8) * CB_ST + pA0] = cA1[0];
        cbuf[(j0 + 9) * CB_ST + pA0] = cA1[1];
        cbuf[(j0 + 8) * CB_ST + pA1] = cA1[2];
        cbuf[(j0 + 9) * CB_ST + pA1] = cA1[3];
        cbuf[(j0 + 0) * CB_ST + pB0] = cB0[0];
        cbuf[(j0 + 1) * CB_ST + pB0] = cB0[1];
        cbuf[(j0 + 0) * CB_ST + pB1] = cB0[2];
        cbuf[(j0 + 1) * CB_ST + pB1] = cB0[3];
        cbuf[(j0 + 8) * CB_ST + pB0] = cB1[0];
        cbuf[(j0 + 9) * CB_ST + pB0] = cB1[1];
        cbuf[(j0 + 8) * CB_ST + pB1] = cB1[2];
        cbuf[(j0 + 9) * CB_ST + pB1] = cB1[3];
    }
    __syncthreads();
    if (chalf == 1) {
        cbuf[(j0 + 0) * CB_ST + pA0] += cA0[0];
        cbuf[(j0 + 1) * CB_ST + pA0] += cA0[1];
        cbuf[(j0 + 0) * CB_ST + pA1] += cA0[2];
        cbuf[(j0 + 1) * CB_ST + pA1] += cA0[3];
        cbuf[(j0 + 8) * CB_ST + pA0] += cA1[0];
        cbuf[(j0 + 9) * CB_ST + pA0] += cA1[1];
        cbuf[(j0 + 8) * CB_ST + pA1] += cA1[2];
        cbuf[(j0 + 9) * CB_ST + pA1] += cA1[3];
        cbuf[(j0 + 0) * CB_ST + pB0] += cB0[0];
        cbuf[(j0 + 1) * CB_ST + pB0] += cB0[1];
        cbuf[(j0 + 0) * CB_ST + pB1] += cB0[2];
        cbuf[(j0 + 1) * CB_ST + pB1] += cB0[3];
        cbuf[(j0 + 8) * CB_ST + pB0] += cB1[0];
        cbuf[(j0 + 9) * CB_ST + pB0] += cB1[1];
        cbuf[(j0 + 8) * CB_ST + pB1] += cB1[2];
        cbuf[(j0 + 9) * CB_ST + pB1] += cB1[3];
    }
    __syncthreads();

#pragma unroll
    for (int e = tid; e < 5 * PTS_PER_BLOCK; e += TPB) {
        const int m = e >> 7;      // 0..4
        const int p = e & 127;
        const int gp = gbase + p;
        if (gp < n) {
            const float2 v = make_float2(cbuf[(2 * m + 0) * CB_ST + p],
                                         cbuf[(2 * m + 1) * CB_ST + p]);
            *reinterpret_cast<float2*>(out + (size_t)m * n * 2 + (size_t)gp * 2) = v;
        }
    }
}

extern "C" void kernel_launch(void* const* d_in, const int* in_sizes, int n_in,
                              void* d_out, int out_size) {
    const float* x = (const float*)d_in[0];        // [N, 2]
    const float* centers = (const float*)d_in[1];  // [256, 2]
    const float* weights = (const float*)d_in[2];  // [5, 256, 2]
    float* out = (float*)d_out;                    // [5, N, 2]

    const int n = in_sizes[0] / 2;
    const int blocks = (n + PTS_PER_BLOCK - 1) / PTS_PER_BLOCK;
    rbf_mma_kernel<<<blocks, TPB>>>(x, centers, weights, out, n);
}

// round 13
// speedup vs baseline: 1.0043x; 1.0043x over previous
#include <cuda_runtime.h>
#include <cuda_fp16.h>
#include <cstdint>

// EnsembleRBF via mma.sync m16n8k16 fp16 (A fp16, B fp16, fp32 accum).
// out[m,n,d] = sum_c exp(-||x_n-c||^2) * sigma^2 * W[m,c,d]
// N=100000, C=256, D=2, M=5.
// R13: 2 point-tiles per block (grid 391 -> whole grid co-resident, staging
// amortized 2x), R8-style simple staging with float4 loads, R11 mainloop.

#define TPB 256
#define TILE_PTS 128
#define TILES_PER_BLOCK 2
#define PTS_PER_BLOCK (TILE_PTS * TILES_PER_BLOCK)
#define C_CENTERS 256
#define HSTEPS 8
#define NSTEPS 16
#define CB_ST 130

__device__ __forceinline__ float ex2a(float v) {
    float r; asm("ex2.approx.ftz.f32 %0, %1;" : "=f"(r) : "f"(v)); return r;
}
// pack {upper=a, lower=b} as f16x2
__device__ __forceinline__ uint32_t hpack(float a, float b) {
    uint32_t d;
    asm("cvt.rn.f16x2.f32 %0, %1, %2;" : "=r"(d) : "f"(a), "f"(b));
    return d;
}

__device__ __forceinline__ void mma16816(float* c,
    uint32_t a0, uint32_t a1, uint32_t a2, uint32_t a3, uint32_t b0, uint32_t b1) {
    asm volatile(
        "mma.sync.aligned.m16n8k16.row.col.f32.f16.f16.f32 "
        "{%0,%1,%2,%3}, {%4,%5,%6,%7}, {%8,%9}, {%0,%1,%2,%3};"
        : "+f"(c[0]), "+f"(c[1]), "+f"(c[2]), "+f"(c[3])
        : "r"(a0), "r"(a1), "r"(a2), "r"(a3), "r"(b0), "r"(b1));
}

__global__ void __launch_bounds__(TPB)
rbf_mma_kernel(const float* __restrict__ x,
               const float* __restrict__ centers,
               const float* __restrict__ weights,
               float* __restrict__ out,
               int n) {
    // gtab[c] = (2*L2E*cx, 2*L2E*cy, -L2E*|c|^2, 0)
    __shared__ float4 gtab[C_CENTERS];                 // 4KB
    // B fragments [step][lane] -> uint4 {t0b0, t0b1, t1b0, t1b1} (fp16)
    __shared__ uint4 bfragH[NSTEPS * 32];              // 8KB
    __shared__ float cbuf[16 * CB_ST];                 // 8.1KB transpose + reduce

    const int tid = threadIdx.x;
    const int lane = tid & 31;
    const int w = tid >> 5;
    const int wq = w & 3;        // point-group within block
    const int chalf = w >> 2;    // which half of centers
    const float L2E = 1.4426950408889634f;

    // ---- stage gtab ----
    for (int c = tid; c < C_CENTERS; c += TPB) {
        const float2 cc = reinterpret_cast<const float2*>(centers)[c];
        gtab[c] = make_float4(2.0f * L2E * cc.x, 2.0f * L2E * cc.y,
                              -L2E * (cc.x * cc.x + cc.y * cc.y), 0.0f);
    }
    // ---- stage B fragments: R8 structure + float4 loads (4 LDG.128/uint4) ----
    for (int e = tid; e < NSTEPS * 32; e += TPB) {
        const int s = e >> 5;
        const int l = e & 31;
        uint32_t hh[4];
#pragma unroll
        for (int t = 0; t < 2; t++) {
#pragma unroll
            for (int b = 0; b < 2; b++) {
                const int j = t * 8 + (l >> 2);              // output column (2m+d)
                const int k = s * 16 + (l & 3) * 2 + b * 8;  // center index
                float w0 = 0.0f, w1 = 0.0f;
                if (j < 10) {
                    // one float4 = {W[m,k,0],W[m,k,1],W[m,k+1,0],W[m,k+1,1]}
                    const float4 F = *reinterpret_cast<const float4*>(
                        weights + (j >> 1) * 512 + k * 2);
                    w0 = (j & 1) ? F.y : F.x;
                    w1 = (j & 1) ? F.w : F.z;
                }
                hh[t * 2 + b] = hpack(w1, w0);   // {upper=k+1, lower=k}
            }
        }
        bfragH[e] = make_uint4(hh[0], hh[1], hh[2], hh[3]);
    }
    __syncthreads();

    const int kb = (lane & 3) * 2;
    const int lp = wq * 32 + (lane >> 2);

#pragma unroll
    for (int tile = 0; tile < TILES_PER_BLOCK; tile++) {
        const int gbase = blockIdx.x * PTS_PER_BLOCK + tile * TILE_PTS;

        // ---- 4 points per lane: tile A rows (lp, lp+8), tile B rows (+16, +24)
        const int q0 = gbase + lp;
        const float2 XA0 = reinterpret_cast<const float2*>(x)[q0 < n ? q0 : (n - 1)];
        const float2 XA1 = reinterpret_cast<const float2*>(x)[(q0 + 8) < n ? (q0 + 8) : (n - 1)];
        const float2 XB0 = reinterpret_cast<const float2*>(x)[(q0 + 16) < n ? (q0 + 16) : (n - 1)];
        const float2 XB1 = reinterpret_cast<const float2*>(x)[(q0 + 24) < n ? (q0 + 24) : (n - 1)];
        // per-point bias: -L2E*|x|^2 - 4  (sigma^2 = 2^-4 folded)
        const float tA0 = fmaf(fmaf(XA0.x, XA0.x, XA0.y * XA0.y), -L2E, -4.0f);
        const float tA1 = fmaf(fmaf(XA1.x, XA1.x, XA1.y * XA1.y), -L2E, -4.0f);
        const float tB0 = fmaf(fmaf(XB0.x, XB0.x, XB0.y * XB0.y), -L2E, -4.0f);
        const float tB1 = fmaf(fmaf(XB1.x, XB1.x, XB1.y * XB1.y), -L2E, -4.0f);

        float cA0[4] = {0.f, 0.f, 0.f, 0.f};  // tile A, cols 0-7
        float cA1[4] = {0.f, 0.f, 0.f, 0.f};  // tile A, cols 8-15
        float cB0[4] = {0.f, 0.f, 0.f, 0.f};  // tile B, cols 0-7
        float cB1[4] = {0.f, 0.f, 0.f, 0.f};  // tile B, cols 8-15

#pragma unroll
        for (int k = 0; k < HSTEPS; k++) {
            const int s = chalf * HSTEPS + k;
            const float4* gp = &gtab[s * 16 + kb];
            const float4 g0 = gp[0], g1 = gp[1], g2 = gp[8], g3 = gp[9];

            const float rA00 = ex2a(fmaf(XA0.x, g0.x, fmaf(XA0.y, g0.y, g0.z)) + tA0);
            const float rA01 = ex2a(fmaf(XA0.x, g1.x, fmaf(XA0.y, g1.y, g1.z)) + tA0);
            const float rA02 = ex2a(fmaf(XA0.x, g2.x, fmaf(XA0.y, g2.y, g2.z)) + tA0);
            const float rA03 = ex2a(fmaf(XA0.x, g3.x, fmaf(XA0.y, g3.y, g3.z)) + tA0);
            const float rA10 = ex2a(fmaf(XA1.x, g0.x, fmaf(XA1.y, g0.y, g0.z)) + tA1);
            const float rA11 = ex2a(fmaf(XA1.x, g1.x, fmaf(XA1.y, g1.y, g1.z)) + tA1);
            const float rA12 = ex2a(fmaf(XA1.x, g2.x, fmaf(XA1.y, g2.y, g2.z)) + tA1);
            const float rA13 = ex2a(fmaf(XA1.x, g3.x, fmaf(XA1.y, g3.y, g3.z)) + tA1);
            const float rB00 = ex2a(fmaf(XB0.x, g0.x, fmaf(XB0.y, g0.y, g0.z)) + tB0);
            const float rB01 = ex2a(fmaf(XB0.x, g1.x, fmaf(XB0.y, g1.y, g1.z)) + tB0);
            const float rB02 = ex2a(fmaf(XB0.x, g2.x, fmaf(XB0.y, g2.y, g2.z)) + tB0);
            const float rB03 = ex2a(fmaf(XB0.x, g3.x, fmaf(XB0.y, g3.y, g3.z)) + tB0);
            const float rB10 = ex2a(fmaf(XB1.x, g0.x, fmaf(XB1.y, g0.y, g0.z)) + tB1);
            const float rB11 = ex2a(fmaf(XB1.x, g1.x, fmaf(XB1.y, g1.y, g1.z)) + tB1);
            const float rB12 = ex2a(fmaf(XB1.x, g2.x, fmaf(XB1.y, g2.y, g2.z)) + tB1);
            const float rB13 = ex2a(fmaf(XB1.x, g3.x, fmaf(XB1.y, g3.y, g3.z)) + tB1);

            // A fragments: {upper = k+1 col, lower = k col}
            const uint32_t aA0 = hpack(rA01, rA00);
            const uint32_t aA1 = hpack(rA11, rA10);
            const uint32_t aA2 = hpack(rA03, rA02);
            const uint32_t aA3 = hpack(rA13, rA12);
            const uint32_t aB0 = hpack(rB01, rB00);
            const uint32_t aB1 = hpack(rB11, rB10);
            const uint32_t aB2 = hpack(rB03, rB02);
            const uint32_t aB3 = hpack(rB13, rB12);

            const uint4 BH = bfragH[s * 32 + lane];

            mma16816(cA0, aA0, aA1, aA2, aA3, BH.x, BH.y);
            mma16816(cA1, aA0, aA1, aA2, aA3, BH.z, BH.w);
            mma16816(cB0, aB0, aB1, aB2, aB3, BH.x, BH.y);
            mma16816(cB1, aB0, aB1, aB2, aB3, BH.z, BH.w);
        }

        // ---- epilogue: merge C-halves in the transpose buffer ----
        const int j0 = (lane & 3) * 2;
        const int pA0 = lp, pA1 = lp + 8, pB0 = lp + 16, pB1 = lp + 24;

        if (chalf == 0) {
            cbuf[(j0 + 0) * CB_ST + pA0] = cA0[0];
            cbuf[(j0 + 1) * CB_ST + pA0] = cA0[1];
            cbuf[(j0 + 0) * CB_ST + pA1] = cA0[2];
            cbuf[(j0 + 1) * CB_ST + pA1] = cA0[3];
            cbuf[(j0 + 8) * CB_ST + pA0] = cA1[0];
            cbuf[(j0 + 9) * CB_ST + pA0] = cA1[1];
            cbuf[(j0 + 8) * CB_ST + pA1] = cA1[2];
            cbuf[(j0 + 9) * CB_ST + pA1] = cA1[3];
            cbuf[(j0 + 0) * CB_ST + pB0] = cB0[0];
            cbuf[(j0 + 1) * CB_ST + pB0] = cB0[1];
            cbuf[(j0 + 0) * CB_ST + pB1] = cB0[2];
            cbuf[(j0 + 1) * CB_ST + pB1] = cB0[3];
            cbuf[(j0 + 8) * CB_ST + pB0] = cB1[0];
            cbuf[(j0 + 9) * CB_ST + pB0] = cB1[1];
            cbuf[(j0 + 8) * CB_ST + pB1] = cB1[2];
            cbuf[(j0 + 9) * CB_ST + pB1] = cB1[3];
        }
        __syncthreads();
        if (chalf == 1) {
            cbuf[(j0 + 0) * CB_ST + pA0] += cA0[0];
            cbuf[(j0 + 1) * CB_ST + pA0] += cA0[1];
            cbuf[(j0 + 0) * CB_ST + pA1] += cA0[2];
            cbuf[(j0 + 1) * CB_ST + pA1] += cA0[3];
            cbuf[(j0 + 8) * CB_ST + pA0] += cA1[0];
            cbuf[(j0 + 9) * CB_ST + pA0] += cA1[1];
            cbuf[(j0 + 8) * CB_ST + pA1] += cA1[2];
            cbuf[(j0 + 9) * CB_ST + pA1] += cA1[3];
            cbuf[(j0 + 0) * CB_ST + pB0] += cB0[0];
            cbuf[(j0 + 1) * CB_ST + pB0] += cB0[1];
            cbuf[(j0 + 0) * CB_ST + pB1] += cB0[2];
            cbuf[(j0 + 1) * CB_ST + pB1] += cB0[3];
            cbuf[(j0 + 8) * CB_ST + pB0] += cB1[0];
            cbuf[(j0 + 9) * CB_ST + pB0] += cB1[1];
            cbuf[(j0 + 8) * CB_ST + pB1] += cB1[2];
            cbuf[(j0 + 9) * CB_ST + pB1] += cB1[3];
        }
        __syncthreads();

#pragma unroll
        for (int e = tid; e < 5 * TILE_PTS; e += TPB) {
            const int m = e >> 7;      // 0..4
            const int p = e & 127;
            const int gp = gbase + p;
            if (gp < n) {
                const float2 v = make_float2(cbuf[(2 * m + 0) * CB_ST + p],
                                             cbuf[(2 * m + 1) * CB_ST + p]);
                *reinterpret_cast<float2*>(out + (size_t)m * n * 2 + (size_t)gp * 2) = v;
            }
        }
        __syncthreads();   // cbuf reuse safety for next tile
    }
}

extern "C" void kernel_launch(void* const* d_in, const int* in_sizes, int n_in,
                              void* d_out, int out_size) {
    const float* x = (const float*)d_in[0];        // [N, 2]
    const float* centers = (const float*)d_in[1];  // [256, 2]
    const float* weights = (const float*)d_in[2];  // [5, 256, 2]
    float* out = (float*)d_out;                    // [5, N, 2]

    const int n = in_sizes[0] / 2;
    const int blocks = (n + PTS_PER_BLOCK - 1) / PTS_PER_BLOCK;
    rbf_mma_kernel<<<blocks, TPB>>>(x, centers, weights, out, n);
}

// round 14
// speedup vs baseline: 1.0087x; 1.0043x over previous
#include <cuda_runtime.h>
#include <cuda_fp16.h>
#include <cstdint>

// EnsembleRBF via mma.sync m16n8k16 fp16 (A fp16, B fp16, fp32 accum).
// out[m,n,d] = sum_c exp(-||x_n-c||^2) * sigma^2 * W[m,c,d]
// N=100000, C=256, D=2, M=5.
// R14: R13 (2 tiles/block, grid 391 co-resident) + register diet:
// __launch_bounds__(256,3) for 3 blocks/SM and a rolled tile loop so the
// register set is reused across tiles (R13's unroll cost 94 regs -> 2 blocks).

#define TPB 256
#define TILE_PTS 128
#define TILES_PER_BLOCK 2
#define PTS_PER_BLOCK (TILE_PTS * TILES_PER_BLOCK)
#define C_CENTERS 256
#define HSTEPS 8
#define NSTEPS 16
#define CB_ST 130

__device__ __forceinline__ float ex2a(float v) {
    float r; asm("ex2.approx.ftz.f32 %0, %1;" : "=f"(r) : "f"(v)); return r;
}
// pack {upper=a, lower=b} as f16x2
__device__ __forceinline__ uint32_t hpack(float a, float b) {
    uint32_t d;
    asm("cvt.rn.f16x2.f32 %0, %1, %2;" : "=r"(d) : "f"(a), "f"(b));
    return d;
}

__device__ __forceinline__ void mma16816(float* c,
    uint32_t a0, uint32_t a1, uint32_t a2, uint32_t a3, uint32_t b0, uint32_t b1) {
    asm volatile(
        "mma.sync.aligned.m16n8k16.row.col.f32.f16.f16.f32 "
        "{%0,%1,%2,%3}, {%4,%5,%6,%7}, {%8,%9}, {%0,%1,%2,%3};"
        : "+f"(c[0]), "+f"(c[1]), "+f"(c[2]), "+f"(c[3])
        : "r"(a0), "r"(a1), "r"(a2), "r"(a3), "r"(b0), "r"(b1));
}

__global__ void __launch_bounds__(TPB, 3)
rbf_mma_kernel(const float* __restrict__ x,
               const float* __restrict__ centers,
               const float* __restrict__ weights,
               float* __restrict__ out,
               int n) {
    // gtab[c] = (2*L2E*cx, 2*L2E*cy, -L2E*|c|^2, 0)
    __shared__ float4 gtab[C_CENTERS];                 // 4KB
    // B fragments [step][lane] -> uint4 {t0b0, t0b1, t1b0, t1b1} (fp16)
    __shared__ uint4 bfragH[NSTEPS * 32];              // 8KB
    __shared__ float cbuf[16 * CB_ST];                 // 8.1KB transpose + reduce

    const int tid = threadIdx.x;
    const int lane = tid & 31;
    const int w = tid >> 5;
    const int wq = w & 3;        // point-group within block
    const int chalf = w >> 2;    // which half of centers
    const float L2E = 1.4426950408889634f;

    // ---- stage gtab ----
    for (int c = tid; c < C_CENTERS; c += TPB) {
        const float2 cc = reinterpret_cast<const float2*>(centers)[c];
        gtab[c] = make_float4(2.0f * L2E * cc.x, 2.0f * L2E * cc.y,
                              -L2E * (cc.x * cc.x + cc.y * cc.y), 0.0f);
    }
    // ---- stage B fragments (float4 loads; cols >= 10 zero) ----
    for (int e = tid; e < NSTEPS * 32; e += TPB) {
        const int s = e >> 5;
        const int l = e & 31;
        uint32_t hh[4];
#pragma unroll
        for (int t = 0; t < 2; t++) {
#pragma unroll
            for (int b = 0; b < 2; b++) {
                const int j = t * 8 + (l >> 2);              // output column (2m+d)
                const int k = s * 16 + (l & 3) * 2 + b * 8;  // center index
                float w0 = 0.0f, w1 = 0.0f;
                if (j < 10) {
                    // one float4 = {W[m,k,0],W[m,k,1],W[m,k+1,0],W[m,k+1,1]}
                    const float4 F = *reinterpret_cast<const float4*>(
                        weights + (j >> 1) * 512 + k * 2);
                    w0 = (j & 1) ? F.y : F.x;
                    w1 = (j & 1) ? F.w : F.z;
                }
                hh[t * 2 + b] = hpack(w1, w0);   // {upper=k+1, lower=k}
            }
        }
        bfragH[e] = make_uint4(hh[0], hh[1], hh[2], hh[3]);
    }
    __syncthreads();

    const int kb = (lane & 3) * 2;
    const int lp = wq * 32 + (lane >> 2);
    const int j0 = (lane & 3) * 2;

#pragma unroll 1
    for (int tile = 0; tile < TILES_PER_BLOCK; tile++) {
        const int gbase = blockIdx.x * PTS_PER_BLOCK + tile * TILE_PTS;

        // ---- 4 points per lane: tile A rows (lp, lp+8), tile B rows (+16, +24)
        const int q0 = gbase + lp;
        const float2 XA0 = reinterpret_cast<const float2*>(x)[q0 < n ? q0 : (n - 1)];
        const float2 XA1 = reinterpret_cast<const float2*>(x)[(q0 + 8) < n ? (q0 + 8) : (n - 1)];
        const float2 XB0 = reinterpret_cast<const float2*>(x)[(q0 + 16) < n ? (q0 + 16) : (n - 1)];
        const float2 XB1 = reinterpret_cast<const float2*>(x)[(q0 + 24) < n ? (q0 + 24) : (n - 1)];
        // per-point bias: -L2E*|x|^2 - 4  (sigma^2 = 2^-4 folded)
        const float tA0 = fmaf(fmaf(XA0.x, XA0.x, XA0.y * XA0.y), -L2E, -4.0f);
        const float tA1 = fmaf(fmaf(XA1.x, XA1.x, XA1.y * XA1.y), -L2E, -4.0f);
        const float tB0 = fmaf(fmaf(XB0.x, XB0.x, XB0.y * XB0.y), -L2E, -4.0f);
        const float tB1 = fmaf(fmaf(XB1.x, XB1.x, XB1.y * XB1.y), -L2E, -4.0f);

        float cA0[4] = {0.f, 0.f, 0.f, 0.f};  // tile A, cols 0-7
        float cA1[4] = {0.f, 0.f, 0.f, 0.f};  // tile A, cols 8-15
        float cB0[4] = {0.f, 0.f, 0.f, 0.f};  // tile B, cols 0-7
        float cB1[4] = {0.f, 0.f, 0.f, 0.f};  // tile B, cols 8-15

#pragma unroll
        for (int k = 0; k < HSTEPS; k++) {
            const int s = chalf * HSTEPS + k;
            const float4* gp = &gtab[s * 16 + kb];
            const float4 g0 = gp[0], g1 = gp[1], g2 = gp[8], g3 = gp[9];

            const float rA00 = ex2a(fmaf(XA0.x, g0.x, fmaf(XA0.y, g0.y, g0.z)) + tA0);
            const float rA01 = ex2a(fmaf(XA0.x, g1.x, fmaf(XA0.y, g1.y, g1.z)) + tA0);
            const float rA02 = ex2a(fmaf(XA0.x, g2.x, fmaf(XA0.y, g2.y, g2.z)) + tA0);
            const float rA03 = ex2a(fmaf(XA0.x, g3.x, fmaf(XA0.y, g3.y, g3.z)) + tA0);
            const float rA10 = ex2a(fmaf(XA1.x, g0.x, fmaf(XA1.y, g0.y, g0.z)) + tA1);
            const float rA11 = ex2a(fmaf(XA1.x, g1.x, fmaf(XA1.y, g1.y, g1.z)) + tA1);
            const float rA12 = ex2a(fmaf(XA1.x, g2.x, fmaf(XA1.y, g2.y, g2.z)) + tA1);
            const float rA13 = ex2a(fmaf(XA1.x, g3.x, fmaf(XA1.y, g3.y, g3.z)) + tA1);
            const float rB00 = ex2a(fmaf(XB0.x, g0.x, fmaf(XB0.y, g0.y, g0.z)) + tB0);
            const float rB01 = ex2a(fmaf(XB0.x, g1.x, fmaf(XB0.y, g1.y, g1.z)) + tB0);
            const float rB02 = ex2a(fmaf(XB0.x, g2.x, fmaf(XB0.y, g2.y, g2.z)) + tB0);
            const float rB03 = ex2a(fmaf(XB0.x, g3.x, fmaf(XB0.y, g3.y, g3.z)) + tB0);
            const float rB10 = ex2a(fmaf(XB1.x, g0.x, fmaf(XB1.y, g0.y, g0.z)) + tB1);
            const float rB11 = ex2a(fmaf(XB1.x, g1.x, fmaf(XB1.y, g1.y, g1.z)) + tB1);
            const float rB12 = ex2a(fmaf(XB1.x, g2.x, fmaf(XB1.y, g2.y, g2.z)) + tB1);
            const float rB13 = ex2a(fmaf(XB1.x, g3.x, fmaf(XB1.y, g3.y, g3.z)) + tB1);

            // A fragments: {upper = k+1 col, lower = k col}
            const uint32_t aA0 = hpack(rA01, rA00);
            const uint32_t aA1 = hpack(rA11, rA10);
            const uint32_t aA2 = hpack(rA03, rA02);
            const uint32_t aA3 = hpack(rA13, rA12);
            const uint32_t aB0 = hpack(rB01, rB00);
            const uint32_t aB1 = hpack(rB11, rB10);
            const uint32_t aB2 = hpack(rB03, rB02);
            const uint32_t aB3 = hpack(rB13, rB12);

            const uint4 BH = bfragH[s * 32 + lane];

            mma16816(cA0, aA0, aA1, aA2, aA3, BH.x, BH.y);
            mma16816(cA1, aA0, aA1, aA2, aA3, BH.z, BH.w);
            mma16816(cB0, aB0, aB1, aB2, aB3, BH.x, BH.y);
            mma16816(cB1, aB0, aB1, aB2, aB3, BH.z, BH.w);
        }

        // ---- epilogue: merge C-halves in the transpose buffer ----
        const int pA0 = lp, pA1 = lp + 8, pB0 = lp + 16, pB1 = lp + 24;

        if (chalf == 0) {
            cbuf[(j0 + 0) * CB_ST + pA0] = cA0[0];
            cbuf[(j0 + 1) * CB_ST + pA0] = cA0[1];
            cbuf[(j0 + 0) * CB_ST + pA1] = cA0[2];
            cbuf[(j0 + 1) * CB_ST + pA1] = cA0[3];
            cbuf[(j0 + 8) * CB_ST + pA0] = cA1[0];
            cbuf[(j0 + 9) * CB_ST + pA0] = cA1[1];
            cbuf[(j0 + 8) * CB_ST + pA1] = cA1[2];
            cbuf[(j0 + 9) * CB_ST + pA1] = cA1[3];
            cbuf[(j0 + 0) * CB_ST + pB0] = cB0[0];
            cbuf[(j0 + 1) * CB_ST + pB0] = cB0[1];
            cbuf[(j0 + 0) * CB_ST + pB1] = cB0[2];
            cbuf[(j0 + 1) * CB_ST + pB1] = cB0[3];
            cbuf[(j0 + 8) * CB_ST + pB0] = cB1[0];
            cbuf[(j0 + 9) * CB_ST + pB0] = cB1[1];
            cbuf[(j0 + 8) * CB_ST + pB1] = cB1[2];
            cbuf[(j0 + 9) * CB_ST + pB1] = cB1[3];
        }
        __syncthreads();
        if (chalf == 1) {
            cbuf[(j0 + 0) * CB_ST + pA0] += cA0[0];
            cbuf[(j0 + 1) * CB_ST + pA0] += cA0[1];
            cbuf[(j0 + 0) * CB_ST + pA1] += cA0[2];
            cbuf[(j0 + 1) * CB_ST + pA1] += cA0[3];
            cbuf[(j0 + 8) * CB_ST + pA0] += cA1[0];
            cbuf[(j0 + 9) * CB_ST + pA0] += cA1[1];
            cbuf[(j0 + 8) * CB_ST + pA1] += cA1[2];
            cbuf[(j0 + 9) * CB_ST + pA1] += cA1[3];
            cbuf[(j0 + 0) * CB_ST + pB0] += cB0[0];
            cbuf[(j0 + 1) * CB_ST + pB0] += cB0[1];
            cbuf[(j0 + 0) * CB_ST + pB1] += cB0[2];
            cbuf[(j0 + 1) * CB_ST + pB1] += cB0[3];
            cbuf[(j0 + 8) * CB_ST + pB0] += cB1[0];
            cbuf[(j0 + 9) * CB_ST + pB0] += cB1[1];
            cbuf[(j0 + 8) * CB_ST + pB1] += cB1[2];
            cbuf[(j0 + 9) * CB_ST + pB1] += cB1[3];
        }
        __syncthreads();

        for (int e = tid; e < 5 * TILE_PTS; e += TPB) {
            const int m = e >> 7;      // 0..4
            const int p = e & 127;
            const int gp = gbase + p;
            if (gp < n) {
                const float2 v = make_float2(cbuf[(2 * m + 0) * CB_ST + p],
                                             cbuf[(2 * m + 1) * CB_ST + p]);
                *reinterpret_cast<float2*>(out + (size_t)m * n * 2 + (size_t)gp * 2) = v;
            }
        }
        __syncthreads();   // cbuf reuse safety for next tile
    }
}

extern "C" void kernel_launch(void* const* d_in, const int* in_sizes, int n_in,
                              void* d_out, int out_size) {
    const float* x = (const float*)d_in[0];        // [N, 2]
    const float* centers = (const float*)d_in[1];  // [256, 2]
    const float* weights = (const float*)d_in[2];  // [5, 256, 2]
    float* out = (float*)d_out;                    // [5, N, 2]

    const int n = in_sizes[0] / 2;
    const int blocks = (n + PTS_PER_BLOCK - 1) / PTS_PER_BLOCK;
    rbf_mma_kernel<<<blocks, TPB>>>(x, centers, weights, out, n);
}